// round 8
// baseline (speedup 1.0000x reference)
#include <cuda_runtime.h>
#include <math.h>

namespace {

constexpr int kB     = 4;      // basis kernels
constexpr int kH     = 8;      // heads
constexpr int kNI    = 16384;  // BATCH * N
constexpr int kBlk   = 128;    // threads per CTA (1 column each)
constexpr int kHPT   = 2;      // heads per CTA
constexpr int kCols  = 128;    // columns per CTA
constexpr int kTT    = 16;     // timesteps per chunk
constexpr int kNBuf  = 2;      // double-buffered input and output
constexpr int kSpkRowB   = kCols * 4;        // 512 B
constexpr int kSpkChunkB = kTT * kSpkRowB;   // 8192 B
constexpr int kOutRowB   = kCols * 4;        // 512 B

// Dynamic SMEM layout (bytes)
constexpr int kOffSpk  = 0;                                  // [2][16][128] f32
constexpr int kSpkSz   = kNBuf * kTT * kCols * 4;            // 16384
constexpr int kOffOut  = kOffSpk + kSpkSz;                   // [2][16][2][128] f32
constexpr int kOutSz   = kNBuf * kTT * kHPT * kCols * 4;     // 32768
constexpr int kOffMbar = kOffOut + kOutSz;                   // 2 x u64
constexpr int kSmemBytes = kOffMbar + 64;

__device__ int g_dt_default = 1;

__device__ __forceinline__ unsigned long long pack2(float lo, float hi) {
    unsigned long long r;
    asm("mov.b64 %0, {%1, %2};" : "=l"(r) : "f"(lo), "f"(hi));
    return r;
}
__device__ __forceinline__ void unpack2(unsigned long long v, float& lo, float& hi) {
    asm("mov.b64 {%0, %1}, %2;" : "=f"(lo), "=f"(hi) : "l"(v));
}
__device__ __forceinline__ unsigned long long fma2(unsigned long long a,
                                                   unsigned long long b,
                                                   unsigned long long c) {
    unsigned long long r;
    asm("fma.rn.f32x2 %0, %1, %2, %3;" : "=l"(r) : "l"(a), "l"(b), "l"(c));
    return r;
}
__device__ __forceinline__ unsigned long long mul2(unsigned long long a,
                                                   unsigned long long b) {
    unsigned long long r;
    asm("mul.rn.f32x2 %0, %1, %2;" : "=l"(r) : "l"(a), "l"(b));
    return r;
}

__device__ __forceinline__ unsigned smem_u32(const void* p) {
    unsigned r;
    asm("{ .reg .u64 t; cvta.to.shared.u64 t, %1; cvt.u32.u64 %0, t; }"
        : "=r"(r) : "l"(p));
    return r;
}
__device__ __forceinline__ void mbar_init(unsigned addr, unsigned count) {
    asm volatile("mbarrier.init.shared.b64 [%0], %1;" :: "r"(addr), "r"(count)
                 : "memory");
}
__device__ __forceinline__ void mbar_expect_tx(unsigned addr, unsigned bytes) {
    asm volatile("mbarrier.arrive.expect_tx.shared.b64 _, [%0], %1;"
                 :: "r"(addr), "r"(bytes) : "memory");
}
__device__ __forceinline__ void mbar_wait(unsigned addr, unsigned parity) {
    asm volatile(
        "{\n\t"
        ".reg .pred P1;\n\t"
        "WAIT_LOOP_%=:\n\t"
        "mbarrier.try_wait.parity.shared::cta.b64 P1, [%0], %1;\n\t"
        "@P1 bra.uni WAIT_DONE_%=;\n\t"
        "bra.uni WAIT_LOOP_%=;\n\t"
        "WAIT_DONE_%=:\n\t"
        "}"
        :: "r"(addr), "r"(parity) : "memory");
}
__device__ __forceinline__ void bulk_g2s(unsigned dst_smem, const void* src,
                                         unsigned bytes, unsigned mbar) {
    asm volatile(
        "cp.async.bulk.shared::cluster.global.mbarrier::complete_tx::bytes "
        "[%0], [%1], %2, [%3];"
        :: "r"(dst_smem), "l"(src), "r"(bytes), "r"(mbar) : "memory");
}
__device__ __forceinline__ void bulk_s2g(const void* dst, unsigned src_smem,
                                         unsigned bytes) {
    asm volatile(
        "cp.async.bulk.global.shared::cta.bulk_group [%0], [%1], %2;"
        :: "l"(dst), "r"(src_smem), "r"(bytes) : "memory");
}

// dt arrives as a scalar; reference passes python int 1. Handle either an
// int32 or a float32 payload robustly (deterministic for fixed input).
__device__ __forceinline__ float resolve_dt(const int* dt_raw) {
    int v = __ldg(dt_raw);
    float f = __int_as_float(v);
    float af = fabsf(f);
    if (af >= 1e-6f && af <= 1e6f) return f;
    return (float)v;
}

// ---------------------------------------------------------------------------
// Fast kernel (B=4, H=8, NI=16384) — refined round-6 structure:
//   * TMA bulk-in (double-buffered, 16-timestep chunks) + TMA bulk-out
//   * output stores issued in PARALLEL by lane 0 of each of the 4 warps,
//     each with its own bulk group + read-guard (no single-thread serial
//     24-op issue burst, per-chunk sync cost halved via kTT=16)
//   * f32x2 math; basis states shared across heads when z0 == 0
// CTA = 128 threads = 128 columns x 2 heads. grid = (128, 4) = 512 CTAs,
// 49 KB dynamic SMEM -> 4 CTAs/SM, single wave.
// ---------------------------------------------------------------------------
__global__ void __launch_bounds__(kBlk)
tb_fast(const float* __restrict__ z0, const float* __restrict__ spikes,
        const float* __restrict__ taus, const float* __restrict__ coeffs,
        const int* __restrict__ dt_raw, float* __restrict__ out, int T)
{
    extern __shared__ __align__(16) char smem[];
    float* sspk = reinterpret_cast<float*>(smem + kOffSpk);   // [2][16][128]
    float* sout = reinterpret_cast<float*>(smem + kOffOut);   // [2][16][2][128]
    unsigned long long* fullb =
        reinterpret_cast<unsigned long long*>(smem + kOffMbar);

    const int tid  = threadIdx.x;
    const int warp = tid >> 5;
    const bool isLane0 = (tid & 31) == 0;
    const int h0   = blockIdx.y * kHPT;
    const int col0 = blockIdx.x * kCols;
    const int col  = col0 + tid;

    const float dt = resolve_dt(dt_raw);

    float d[kB];
#pragma unroll
    for (int k = 0; k < kB; ++k)
        d[k] = (float)exp(-(double)dt / (double)__ldg(&taus[k]));

    const unsigned long long d01 = pack2(d[0], d[1]);
    const unsigned long long d23 = pack2(d[2], d[3]);
    unsigned long long c01[kHPT], c23[kHPT], z01[kHPT], z23[kHPT];
    bool allz = true;
#pragma unroll
    for (int hh = 0; hh < kHPT; ++hh) {
        const int h = h0 + hh;
        c01[hh] = pack2(__ldg(&coeffs[h * kB + 0]), __ldg(&coeffs[h * kB + 1]));
        c23[hh] = pack2(__ldg(&coeffs[h * kB + 2]), __ldg(&coeffs[h * kB + 3]));
        const float4 zi = *reinterpret_cast<const float4*>(
            z0 + ((size_t)h * kNI + col) * kB);
        z01[hh] = pack2(zi.x, zi.y);
        z23[hh] = pack2(zi.z, zi.w);
        allz = allz && (zi.x == 0.f && zi.y == 0.f && zi.z == 0.f &&
                        zi.w == 0.f);
    }

    const int nChunks = T / kTT;

    // mbarrier init + prologue fills (2 chunks).
    if (tid == 0) {
#pragma unroll
        for (int b = 0; b < kNBuf; ++b) mbar_init(smem_u32(&fullb[b]), 1);
        asm volatile("fence.proxy.async;" ::: "memory");
#pragma unroll
        for (int b = 0; b < kNBuf; ++b) {
            mbar_expect_tx(smem_u32(&fullb[b]), kSpkChunkB);
            for (int j = 0; j < kTT; ++j)
                bulk_g2s(smem_u32(&sspk[(b * kTT + j) * kCols]),
                         spikes + (size_t)(b * kTT + j) * kNI + col0,
                         kSpkRowB, smem_u32(&fullb[b]));
        }
    }
    __syncthreads();

    for (int c = 0; c < nChunks; ++c) {
        const int buf = c & 1;
        const unsigned par = (unsigned)((c >> 1) & 1);
        float* sob = sout + (size_t)buf * kTT * kHPT * kCols;
        const float* sib = sspk + (size_t)buf * kTT * kCols;

        // Reuse guard: each issuer waits for its own group from chunk c-2
        // to finish READING sout[buf].
        if (isLane0)
            asm volatile("cp.async.bulk.wait_group.read 1;" ::: "memory");
        __syncthreads();

        // Wait for this chunk's spike tile.
        mbar_wait(smem_u32(&fullb[buf]), par);

        if (allz) {
#pragma unroll
            for (int j = 0; j < kTT; ++j) {
                const float s = sib[j * kCols + tid];
                const unsigned long long ss = pack2(s, s);
                z01[0] = fma2(d01, z01[0], ss);
                z23[0] = fma2(d23, z23[0], ss);
#pragma unroll
                for (int hh = 0; hh < kHPT; ++hh) {
                    const unsigned long long p =
                        fma2(c23[hh], z23[0], mul2(c01[hh], z01[0]));
                    float lo, hi;
                    unpack2(p, lo, hi);
                    sob[(j * kHPT + hh) * kCols + tid] = lo + hi;
                }
            }
        } else {
#pragma unroll
            for (int j = 0; j < kTT; ++j) {
                const float s = sib[j * kCols + tid];
                const unsigned long long ss = pack2(s, s);
#pragma unroll
                for (int hh = 0; hh < kHPT; ++hh) {
                    z01[hh] = fma2(d01, z01[hh], ss);
                    z23[hh] = fma2(d23, z23[hh], ss);
                    const unsigned long long p =
                        fma2(c23[hh], z23[hh], mul2(c01[hh], z01[hh]));
                    float lo, hi;
                    unpack2(p, lo, hi);
                    sob[(j * kHPT + hh) * kCols + tid] = lo + hi;
                }
            }
        }

        asm volatile("fence.proxy.async.shared::cta;" ::: "memory");
        __syncthreads();

        // Parallel store issuance: warp w's lane 0 handles rows r = w, w+4, ...
        if (isLane0) {
            const int tbase = c * kTT;
#pragma unroll
            for (int r = 0; r < kTT * kHPT / 4; ++r) {
                const int row = r * 4 + warp;
                const int j = row >> 1;
                const int hh = row & 1;
                bulk_s2g(out + ((size_t)(tbase + j) * kH + h0 + hh) * kNI +
                             col0,
                         smem_u32(&sob[row * kCols]), kOutRowB);
            }
            asm volatile("cp.async.bulk.commit_group;" ::: "memory");
        }

        // Refill this input buffer for chunk c+2 (all threads finished
        // reading sspk[buf] before the fence+sync above).
        if (tid == 0 && c + kNBuf < nChunks) {
            const int cn = c + kNBuf;
            mbar_expect_tx(smem_u32(&fullb[buf]), kSpkChunkB);
            for (int j = 0; j < kTT; ++j)
                bulk_g2s(smem_u32(&sspk[(buf * kTT + j) * kCols]),
                         spikes + (size_t)(cn * kTT + j) * kNI + col0,
                         kSpkRowB, smem_u32(&fullb[buf]));
        }
    }

    if (isLane0)
        asm volatile("cp.async.bulk.wait_group 0;" ::: "memory");
}

// ---------------------------------------------------------------------------
// Generic fallback (any shapes, Bn <= 16): one thread per (head, idx).
// ---------------------------------------------------------------------------
__global__ void tb_generic(const float* __restrict__ z0,
                           const float* __restrict__ spikes,
                           const float* __restrict__ taus,
                           const float* __restrict__ coeffs,
                           const int* __restrict__ dt_raw,
                           float* __restrict__ out,
                           int T, int NI, int Hn, int Bn)
{
    const int gid = blockIdx.x * blockDim.x + threadIdx.x;
    if (gid >= NI * Hn) return;
    const int idx = gid % NI;
    const int h   = gid / NI;

    const float dt = resolve_dt(dt_raw);

    constexpr int BMAX = 16;
    float z[BMAX], dk[BMAX], ck[BMAX];
    const int Bc = Bn < BMAX ? Bn : BMAX;
    for (int k = 0; k < Bc; ++k) {
        dk[k] = (float)exp(-(double)dt / (double)taus[k]);
        ck[k] = coeffs[h * Bn + k];
        z[k]  = z0[((size_t)h * NI + idx) * Bn + k];
    }
    const float* sp = spikes + idx;
    float* op = out + (size_t)h * NI + idx;
    for (int t = 0; t < T; ++t) {
        const float s = sp[(size_t)t * NI];
        float r = 0.0f;
        for (int k = 0; k < Bc; ++k) {
            z[k] = fmaf(dk[k], z[k], s);
            r = fmaf(ck[k], z[k], r);
        }
        op[(size_t)t * Hn * NI] = r;
    }
}

}  // namespace

extern "C" void kernel_launch(void* const* d_in, const int* in_sizes, int n_in,
                              void* d_out, int out_size)
{
    const float* z0     = (const float*)d_in[0];
    const float* spikes = (const float*)d_in[1];
    const float* taus   = (const float*)d_in[2];
    const float* coeffs = (const float*)d_in[3];

    const int* dt_ptr;
    if (n_in >= 5) {
        dt_ptr = (const int*)d_in[4];
    } else {
        static int* p = nullptr;
        if (!p) cudaGetSymbolAddress((void**)&p, g_dt_default);
        dt_ptr = p;
    }

    float* out = (float*)d_out;

    const int Bn = in_sizes[2];
    const int Hn = in_sizes[3] / Bn;
    const int NI = in_sizes[0] / (Hn * Bn);
    const int T  = in_sizes[1] / NI;

    if (Bn == kB && Hn == kH && NI == kNI && (T % kTT) == 0 &&
        T >= kTT * kNBuf) {
        cudaFuncSetAttribute(tb_fast,
                             cudaFuncAttributeMaxDynamicSharedMemorySize,
                             kSmemBytes);
        dim3 grid(kNI / kCols, kH / kHPT);
        tb_fast<<<grid, kBlk, kSmemBytes>>>(z0, spikes, taus, coeffs, dt_ptr,
                                            out, T);
    } else {
        const int threads = NI * Hn;
        tb_generic<<<(threads + 127) / 128, 128>>>(
            z0, spikes, taus, coeffs, dt_ptr, out, T, NI, Hn, Bn);
    }
}

// round 9
// speedup vs baseline: 1.2289x; 1.2289x over previous
#include <cuda_runtime.h>
#include <cuda.h>
#include <math.h>

namespace {

constexpr int kB     = 4;      // basis kernels
constexpr int kH     = 8;      // heads
constexpr int kNI    = 16384;  // BATCH * N
constexpr int kBlk   = 128;    // threads per CTA (1 column each)
constexpr int kHPT   = 2;      // heads per CTA
constexpr int kCols  = 128;    // columns per CTA
constexpr int kTT    = 8;      // timesteps per chunk
constexpr int kNBuf  = 3;      // triple-buffered in and out
constexpr int kSpkRowB   = kCols * 4;        // 512 B
constexpr int kSpkChunkB = kTT * kSpkRowB;   // 4096 B
constexpr int kOutRowB   = kCols * 4;        // 512 B

__device__ int g_dt_default = 1;

__device__ __forceinline__ unsigned long long pack2(float lo, float hi) {
    unsigned long long r;
    asm("mov.b64 %0, {%1, %2};" : "=l"(r) : "f"(lo), "f"(hi));
    return r;
}
__device__ __forceinline__ void unpack2(unsigned long long v, float& lo, float& hi) {
    asm("mov.b64 {%0, %1}, %2;" : "=f"(lo), "=f"(hi) : "l"(v));
}
__device__ __forceinline__ unsigned long long fma2(unsigned long long a,
                                                   unsigned long long b,
                                                   unsigned long long c) {
    unsigned long long r;
    asm("fma.rn.f32x2 %0, %1, %2, %3;" : "=l"(r) : "l"(a), "l"(b), "l"(c));
    return r;
}
__device__ __forceinline__ unsigned long long mul2(unsigned long long a,
                                                   unsigned long long b) {
    unsigned long long r;
    asm("mul.rn.f32x2 %0, %1, %2;" : "=l"(r) : "l"(a), "l"(b));
    return r;
}

__device__ __forceinline__ unsigned smem_u32(const void* p) {
    unsigned r;
    asm("{ .reg .u64 t; cvta.to.shared.u64 t, %1; cvt.u32.u64 %0, t; }"
        : "=r"(r) : "l"(p));
    return r;
}
__device__ __forceinline__ void mbar_init(unsigned addr, unsigned count) {
    asm volatile("mbarrier.init.shared.b64 [%0], %1;" :: "r"(addr), "r"(count)
                 : "memory");
}
__device__ __forceinline__ void mbar_expect_tx(unsigned addr, unsigned bytes) {
    asm volatile("mbarrier.arrive.expect_tx.shared.b64 _, [%0], %1;"
                 :: "r"(addr), "r"(bytes) : "memory");
}
__device__ __forceinline__ void mbar_wait(unsigned addr, unsigned parity) {
    asm volatile(
        "{\n\t"
        ".reg .pred P1;\n\t"
        "WAIT_LOOP_%=:\n\t"
        "mbarrier.try_wait.parity.shared::cta.b64 P1, [%0], %1;\n\t"
        "@P1 bra.uni WAIT_DONE_%=;\n\t"
        "bra.uni WAIT_LOOP_%=;\n\t"
        "WAIT_DONE_%=:\n\t"
        "}"
        :: "r"(addr), "r"(parity) : "memory");
}
__device__ __forceinline__ void bulk_g2s(unsigned dst_smem, const void* src,
                                         unsigned bytes, unsigned mbar) {
    asm volatile(
        "cp.async.bulk.shared::cluster.global.mbarrier::complete_tx::bytes "
        "[%0], [%1], %2, [%3];"
        :: "r"(dst_smem), "l"(src), "r"(bytes), "r"(mbar) : "memory");
}
__device__ __forceinline__ void bulk_s2g(const void* dst, unsigned src_smem,
                                         unsigned bytes) {
    asm volatile(
        "cp.async.bulk.global.shared::cta.bulk_group [%0], [%1], %2;"
        :: "l"(dst), "r"(src_smem), "r"(bytes) : "memory");
}
__device__ __forceinline__ void tma_ld_2d(unsigned dst_smem,
                                          const CUtensorMap* tm,
                                          int x, int y, unsigned mbar) {
    asm volatile(
        "cp.async.bulk.tensor.2d.shared::cta.global.tile."
        "mbarrier::complete_tx::bytes [%0], [%1, {%2, %3}], [%4];"
        :: "r"(dst_smem), "l"(tm), "r"(x), "r"(y), "r"(mbar) : "memory");
}
__device__ __forceinline__ void tma_st_3d(const CUtensorMap* tm,
                                          int x, int y, int z,
                                          unsigned src_smem) {
    asm volatile(
        "cp.async.bulk.tensor.3d.global.shared::cta.tile.bulk_group "
        "[%0, {%1, %2, %3}], [%4];"
        :: "l"(tm), "r"(x), "r"(y), "r"(z), "r"(src_smem) : "memory");
}

// dt arrives as a scalar; reference passes python int 1. Handle either an
// int32 or a float32 payload robustly (deterministic for fixed input).
__device__ __forceinline__ float resolve_dt(const int* dt_raw) {
    int v = __ldg(dt_raw);
    float f = __int_as_float(v);
    float af = fabsf(f);
    if (af >= 1e-6f && af <= 1e6f) return f;
    return (float)v;
}

// ---------------------------------------------------------------------------
// Round-9 fast kernel: identical structure/math to round 6 (the best so far)
// except the per-chunk 24 serialized cp.async.bulk row ops are replaced by
// TWO TMA tensor-tile ops:
//   input : 2D tile (128 cols x 8 t)            -> 1 UTMALDG / chunk
//   output: 3D tile (128 cols x 2 heads x 8 t)  -> 1 UTMASTG / chunk
// CTA = 128 threads = 128 columns x 2 heads. grid = (128, 4) = 512 CTAs.
// ---------------------------------------------------------------------------
__global__ void __launch_bounds__(kBlk)
tb_fast_tma(const __grid_constant__ CUtensorMap tmS,
            const __grid_constant__ CUtensorMap tmO,
            const float* __restrict__ z0,
            const float* __restrict__ taus,
            const float* __restrict__ coeffs,
            const int* __restrict__ dt_raw, int T)
{
    __shared__ __align__(128) float sspk[kNBuf][kTT][kCols];
    __shared__ __align__(128) float sout[kNBuf][kTT][kHPT][kCols];
    __shared__ __align__(8) unsigned long long fullb[kNBuf];

    const int tid  = threadIdx.x;
    const int h0   = blockIdx.y * kHPT;
    const int col0 = blockIdx.x * kCols;
    const int col  = col0 + tid;

    const float dt = resolve_dt(dt_raw);

    float d[kB];
#pragma unroll
    for (int k = 0; k < kB; ++k)
        d[k] = (float)exp(-(double)dt / (double)__ldg(&taus[k]));

    const unsigned long long d01 = pack2(d[0], d[1]);
    const unsigned long long d23 = pack2(d[2], d[3]);
    unsigned long long c01[kHPT], c23[kHPT], z01[kHPT], z23[kHPT];
#pragma unroll
    for (int hh = 0; hh < kHPT; ++hh) {
        const int h = h0 + hh;
        c01[hh] = pack2(__ldg(&coeffs[h * kB + 0]), __ldg(&coeffs[h * kB + 1]));
        c23[hh] = pack2(__ldg(&coeffs[h * kB + 2]), __ldg(&coeffs[h * kB + 3]));
        const float4 zi = *reinterpret_cast<const float4*>(
            z0 + ((size_t)h * kNI + col) * kB);
        z01[hh] = pack2(zi.x, zi.y);
        z23[hh] = pack2(zi.z, zi.w);
    }

    const int nChunks = T / kTT;

    // mbarrier init + prologue loads (3 chunks of lookahead).
    if (tid == 0) {
#pragma unroll
        for (int b = 0; b < kNBuf; ++b) mbar_init(smem_u32(&fullb[b]), 1);
        asm volatile("fence.proxy.async;" ::: "memory");
#pragma unroll
        for (int b = 0; b < kNBuf; ++b) {
            mbar_expect_tx(smem_u32(&fullb[b]), kSpkChunkB);
            tma_ld_2d(smem_u32(&sspk[b][0][0]), &tmS, col0, b * kTT,
                      smem_u32(&fullb[b]));
        }
    }
    __syncthreads();

    for (int c = 0; c < nChunks; ++c) {
        const int buf = c % kNBuf;
        const unsigned par = (unsigned)((c / kNBuf) & 1);

        // Output-buffer reuse guard: <=2 tensor-store groups outstanding.
        if (tid == 0)
            asm volatile("cp.async.bulk.wait_group.read %0;" :: "n"(kNBuf - 1)
                         : "memory");
        __syncthreads();

        // Wait for this chunk's spike tile.
        mbar_wait(smem_u32(&fullb[buf]), par);

#pragma unroll
        for (int j = 0; j < kTT; ++j) {
            const float s = sspk[buf][j][tid];
            const unsigned long long ss = pack2(s, s);
#pragma unroll
            for (int hh = 0; hh < kHPT; ++hh) {
                z01[hh] = fma2(d01, z01[hh], ss);
                z23[hh] = fma2(d23, z23[hh], ss);
                const unsigned long long p =
                    fma2(c23[hh], z23[hh], mul2(c01[hh], z01[hh]));
                float lo, hi;
                unpack2(p, lo, hi);
                sout[buf][j][hh][tid] = lo + hi;
            }
        }

        asm volatile("fence.proxy.async.shared::cta;" ::: "memory");
        __syncthreads();

        if (tid == 0) {
            // One 3D tensor store covers all 16 (t, head) rows of this chunk.
            tma_st_3d(&tmO, col0, h0, c * kTT, smem_u32(&sout[buf][0][0][0]));
            asm volatile("cp.async.bulk.commit_group;" ::: "memory");

            // Refill this spike buffer for chunk c + 3.
            const int cn = c + kNBuf;
            if (cn < nChunks) {
                mbar_expect_tx(smem_u32(&fullb[buf]), kSpkChunkB);
                tma_ld_2d(smem_u32(&sspk[buf][0][0]), &tmS, col0, cn * kTT,
                          smem_u32(&fullb[buf]));
            }
        }
    }

    if (tid == 0)
        asm volatile("cp.async.bulk.wait_group %0;" :: "n"(0) : "memory");
}

// ---------------------------------------------------------------------------
// Round-6 bulk kernel, kept verbatim as fallback if the tensor-map encode
// entry point is unavailable (known-good at 71.4 us ncu).
// ---------------------------------------------------------------------------
__global__ void __launch_bounds__(kBlk)
tb_fast_bulk(const float* __restrict__ z0, const float* __restrict__ spikes,
             const float* __restrict__ taus, const float* __restrict__ coeffs,
             const int* __restrict__ dt_raw, float* __restrict__ out, int T)
{
    __shared__ __align__(16) float sspk[kNBuf][kTT][kCols];
    __shared__ __align__(16) float sout[kNBuf][kTT][kHPT][kCols];
    __shared__ __align__(8) unsigned long long mbar[kNBuf];

    const int tid  = threadIdx.x;
    const int h0   = blockIdx.y * kHPT;
    const int col0 = blockIdx.x * kCols;
    const int col  = col0 + tid;

    const float dt = resolve_dt(dt_raw);

    float d[kB];
#pragma unroll
    for (int k = 0; k < kB; ++k)
        d[k] = (float)exp(-(double)dt / (double)__ldg(&taus[k]));

    const unsigned long long d01 = pack2(d[0], d[1]);
    const unsigned long long d23 = pack2(d[2], d[3]);
    unsigned long long c01[kHPT], c23[kHPT], z01[kHPT], z23[kHPT];
#pragma unroll
    for (int hh = 0; hh < kHPT; ++hh) {
        const int h = h0 + hh;
        c01[hh] = pack2(__ldg(&coeffs[h * kB + 0]), __ldg(&coeffs[h * kB + 1]));
        c23[hh] = pack2(__ldg(&coeffs[h * kB + 2]), __ldg(&coeffs[h * kB + 3]));
        const float4 zi = *reinterpret_cast<const float4*>(
            z0 + ((size_t)h * kNI + col) * kB);
        z01[hh] = pack2(zi.x, zi.y);
        z23[hh] = pack2(zi.z, zi.w);
    }

    const int nChunks = T / kTT;

    if (tid == 0) {
#pragma unroll
        for (int b = 0; b < kNBuf; ++b) mbar_init(smem_u32(&mbar[b]), 1);
        asm volatile("fence.proxy.async;" ::: "memory");
#pragma unroll
        for (int b = 0; b < kNBuf; ++b) {
            mbar_expect_tx(smem_u32(&mbar[b]), kSpkChunkB);
#pragma unroll
            for (int j = 0; j < kTT; ++j)
                bulk_g2s(smem_u32(&sspk[b][j][0]),
                         spikes + (size_t)(b * kTT + j) * kNI + col0,
                         kSpkRowB, smem_u32(&mbar[b]));
        }
    }
    __syncthreads();

    for (int c = 0; c < nChunks; ++c) {
        const int buf = c % kNBuf;

        if (tid == 0)
            asm volatile("cp.async.bulk.wait_group.read %0;" :: "n"(kNBuf - 1)
                         : "memory");
        __syncthreads();

        mbar_wait(smem_u32(&mbar[buf]), (c / kNBuf) & 1);

#pragma unroll
        for (int j = 0; j < kTT; ++j) {
            const float s = sspk[buf][j][tid];
            const unsigned long long ss = pack2(s, s);
#pragma unroll
            for (int hh = 0; hh < kHPT; ++hh) {
                z01[hh] = fma2(d01, z01[hh], ss);
                z23[hh] = fma2(d23, z23[hh], ss);
                const unsigned long long p =
                    fma2(c23[hh], z23[hh], mul2(c01[hh], z01[hh]));
                float lo, hi;
                unpack2(p, lo, hi);
                sout[buf][j][hh][tid] = lo + hi;
            }
        }

        asm volatile("fence.proxy.async.shared::cta;" ::: "memory");
        __syncthreads();

        if (tid == 0) {
            const int tbase = c * kTT;
#pragma unroll
            for (int j = 0; j < kTT; ++j) {
#pragma unroll
                for (int hh = 0; hh < kHPT; ++hh) {
                    bulk_s2g(out + ((size_t)(tbase + j) * kH + h0 + hh) * kNI
                                 + col0,
                             smem_u32(&sout[buf][j][hh][0]), kOutRowB);
                }
            }
            asm volatile("cp.async.bulk.commit_group;" ::: "memory");

            const int cn = c + kNBuf;
            if (cn < nChunks) {
                mbar_expect_tx(smem_u32(&mbar[buf]), kSpkChunkB);
#pragma unroll
                for (int j = 0; j < kTT; ++j)
                    bulk_g2s(smem_u32(&sspk[buf][j][0]),
                             spikes + (size_t)(cn * kTT + j) * kNI + col0,
                             kSpkRowB, smem_u32(&mbar[buf]));
            }
        }
    }

    if (tid == 0)
        asm volatile("cp.async.bulk.wait_group %0;" :: "n"(0) : "memory");
}

// ---------------------------------------------------------------------------
// Generic fallback (any shapes, Bn <= 16): one thread per (head, idx).
// ---------------------------------------------------------------------------
__global__ void tb_generic(const float* __restrict__ z0,
                           const float* __restrict__ spikes,
                           const float* __restrict__ taus,
                           const float* __restrict__ coeffs,
                           const int* __restrict__ dt_raw,
                           float* __restrict__ out,
                           int T, int NI, int Hn, int Bn)
{
    const int gid = blockIdx.x * blockDim.x + threadIdx.x;
    if (gid >= NI * Hn) return;
    const int idx = gid % NI;
    const int h   = gid / NI;

    const float dt = resolve_dt(dt_raw);

    constexpr int BMAX = 16;
    float z[BMAX], dk[BMAX], ck[BMAX];
    const int Bc = Bn < BMAX ? Bn : BMAX;
    for (int k = 0; k < Bc; ++k) {
        dk[k] = (float)exp(-(double)dt / (double)taus[k]);
        ck[k] = coeffs[h * Bn + k];
        z[k]  = z0[((size_t)h * NI + idx) * Bn + k];
    }
    const float* sp = spikes + idx;
    float* op = out + (size_t)h * NI + idx;
    for (int t = 0; t < T; ++t) {
        const float s = sp[(size_t)t * NI];
        float r = 0.0f;
        for (int k = 0; k < Bc; ++k) {
            z[k] = fmaf(dk[k], z[k], s);
            r = fmaf(ck[k], z[k], r);
        }
        op[(size_t)t * Hn * NI] = r;
    }
}

using EncodeFn = CUresult (*)(CUtensorMap*, CUtensorMapDataType, cuuint32_t,
                              void*, const cuuint64_t*, const cuuint64_t*,
                              const cuuint32_t*, const cuuint32_t*,
                              CUtensorMapInterleave, CUtensorMapSwizzle,
                              CUtensorMapL2promotion, CUtensorMapFloatOOBfill);

static EncodeFn get_encode_fn() {
    void* fn = nullptr;
    cudaDriverEntryPointQueryResult st = cudaDriverEntryPointSymbolNotFound;
    if (cudaGetDriverEntryPointByVersion("cuTensorMapEncodeTiled", &fn, 12000,
                                         cudaEnableDefault, &st) != cudaSuccess)
        return nullptr;
    if (st != cudaDriverEntryPointSuccess) return nullptr;
    return reinterpret_cast<EncodeFn>(fn);
}

}  // namespace

extern "C" void kernel_launch(void* const* d_in, const int* in_sizes, int n_in,
                              void* d_out, int out_size)
{
    const float* z0     = (const float*)d_in[0];
    const float* spikes = (const float*)d_in[1];
    const float* taus   = (const float*)d_in[2];
    const float* coeffs = (const float*)d_in[3];

    const int* dt_ptr;
    if (n_in >= 5) {
        dt_ptr = (const int*)d_in[4];
    } else {
        static int* p = nullptr;
        if (!p) cudaGetSymbolAddress((void**)&p, g_dt_default);
        dt_ptr = p;
    }

    float* out = (float*)d_out;

    const int Bn = in_sizes[2];
    const int Hn = in_sizes[3] / Bn;
    const int NI = in_sizes[0] / (Hn * Bn);
    const int T  = in_sizes[1] / NI;

    if (Bn == kB && Hn == kH && NI == kNI && (T % kTT) == 0 &&
        T >= kTT * kNBuf) {
        dim3 grid(kNI / kCols, kH / kHPT);

        EncodeFn enc = get_encode_fn();
        bool ok = false;
        CUtensorMap tmS{}, tmO{};
        if (enc) {
            // Spikes viewed as 2D [T, NI]; tile (128 cols, 8 t).
            cuuint64_t sdims[2] = {(cuuint64_t)kNI, (cuuint64_t)T};
            cuuint64_t sstr[1]  = {(cuuint64_t)kNI * 4};
            cuuint32_t sbox[2]  = {kCols, kTT};
            cuuint32_t ones[3]  = {1, 1, 1};
            CUresult r1 = enc(&tmS, CU_TENSOR_MAP_DATA_TYPE_FLOAT32, 2,
                              (void*)spikes, sdims, sstr, sbox, ones,
                              CU_TENSOR_MAP_INTERLEAVE_NONE,
                              CU_TENSOR_MAP_SWIZZLE_NONE,
                              CU_TENSOR_MAP_L2_PROMOTION_L2_128B,
                              CU_TENSOR_MAP_FLOAT_OOB_FILL_NONE);
            // Output viewed as 3D [T, H, NI]; tile (128 cols, 2 heads, 8 t).
            cuuint64_t odims[3] = {(cuuint64_t)kNI, (cuuint64_t)kH,
                                   (cuuint64_t)T};
            cuuint64_t ostr[2]  = {(cuuint64_t)kNI * 4,
                                   (cuuint64_t)kH * kNI * 4};
            cuuint32_t obox[3]  = {kCols, kHPT, kTT};
            CUresult r2 = enc(&tmO, CU_TENSOR_MAP_DATA_TYPE_FLOAT32, 3,
                              (void*)out, odims, ostr, obox, ones,
                              CU_TENSOR_MAP_INTERLEAVE_NONE,
                              CU_TENSOR_MAP_SWIZZLE_NONE,
                              CU_TENSOR_MAP_L2_PROMOTION_L2_128B,
                              CU_TENSOR_MAP_FLOAT_OOB_FILL_NONE);
            ok = (r1 == CUDA_SUCCESS) && (r2 == CUDA_SUCCESS);
        }

        if (ok) {
            tb_fast_tma<<<grid, kBlk>>>(tmS, tmO, z0, taus, coeffs, dt_ptr, T);
        } else {
            tb_fast_bulk<<<grid, kBlk>>>(z0, spikes, taus, coeffs, dt_ptr,
                                         out, T);
        }
    } else {
        const int threads = NI * Hn;
        tb_generic<<<(threads + 127) / 128, 128>>>(
            z0, spikes, taus, coeffs, dt_ptr, out, T, NI, Hn, Bn);
    }
}